// round 8
// baseline (speedup 1.0000x reference)
#include <cuda_runtime.h>
#include <cuda_bf16.h>
#include <cstdint>
#include <math.h>

#define Bb 128
#define Tt 512
#define Ee 256
#define Hh 128
#define FOURH 512
#define Vv 32000
#define KP 768

typedef unsigned long long u64t;
typedef __nv_bfloat16 bf16;

// ---------------- static scratch ----------------
__device__ float g_xw[(size_t)2 * Tt * Bb * FOURH];      // [dir][t*128+b][4H]
__device__ __align__(16) bf16 g_ehi[(size_t)Vv * Ee];
__device__ __align__(16) bf16 g_elo[(size_t)Vv * Ee];
__device__ __align__(16) bf16 g_Wt[2][KP][FOURH];        // [dir][k'][n]

// ---------------- helpers ----------------
__device__ __forceinline__ u64t pk2(float lo, float hi) {
    u64t r; asm("mov.b64 %0, {%1, %2};" : "=l"(r) : "f"(lo), "f"(hi)); return r;
}
__device__ __forceinline__ void upk2(u64t v, float& lo, float& hi) {
    asm("mov.b64 {%0, %1}, %2;" : "=f"(lo), "=f"(hi) : "l"(v));
}
#define FFMA2(acc, a, b) asm("fma.rn.f32x2 %0, %1, %2, %0;" : "+l"(acc) : "l"(a), "l"(b))
#define ADDF2(acc, a)    asm("add.rn.f32x2 %0, %0, %1;" : "+l"(acc) : "l"(a))
__device__ __forceinline__ float sigmoid_f(float x) { return __fdividef(1.0f, 1.0f + __expf(-x)); }
__device__ __forceinline__ float tanh_f(float x)    { return __fdividef(2.0f, 1.0f + __expf(-2.0f * x)) - 1.0f; }
__device__ __forceinline__ uint32_t smem_u32(const void* p) {
    uint32_t a;
    asm("{ .reg .u64 t; cvta.to.shared.u64 t, %1; cvt.u32.u64 %0, t; }" : "=r"(a) : "l"(p));
    return a;
}
__device__ __forceinline__ void st_cluster_u64(uint32_t laddr, int rank, u64t v) {
    asm volatile(
        "{ .reg .b32 ra; mapa.shared::cluster.u32 ra, %0, %1; "
        "st.shared::cluster.b64 [ra], %2; }"
        :: "r"(laddr), "r"(rank), "l"(v) : "memory");
}
__device__ __forceinline__ void mbar_arrive_rel(uint32_t laddr, int rank) {
    asm volatile(
        "{ .reg .b32 ra; mapa.shared::cluster.u32 ra, %0, %1; "
        "mbarrier.arrive.release.cluster.shared::cluster.b64 _, [ra]; }"
        :: "r"(laddr), "r"(rank) : "memory");
}
__device__ __forceinline__ void mbar_wait_acq(uint32_t mb, uint32_t parity) {
    asm volatile(
        "{\n\t.reg .pred P1;\n\t"
        "WL_%=:\n\t"
        "mbarrier.try_wait.parity.acquire.cluster.shared::cta.b64 P1, [%0], %1, 0x989680;\n\t"
        "@P1 bra.uni WD_%=;\n\t"
        "bra.uni WL_%=;\n\t"
        "WD_%=:\n\t}" :: "r"(mb), "r"(parity) : "memory");
}
#define MBAR_INIT(a, n) \
    asm volatile("mbarrier.init.shared.b64 [%0], %1;" :: "r"(a), "r"((uint32_t)(n)) : "memory")
#define CLUSTER_SYNC() do { \
    asm volatile("barrier.cluster.arrive.aligned;" ::: "memory"); \
    asm volatile("barrier.cluster.wait.aligned;" ::: "memory"); \
} while (0)

#define LDSM_X4(r0, r1, r2, r3, addr) \
    asm volatile("ldmatrix.sync.aligned.m8n8.x4.shared.b16 {%0,%1,%2,%3}, [%4];" \
                 : "=r"(r0), "=r"(r1), "=r"(r2), "=r"(r3) : "r"(addr))
#define LDSM_X4T(r0, r1, r2, r3, addr) \
    asm volatile("ldmatrix.sync.aligned.m8n8.x4.trans.shared.b16 {%0,%1,%2,%3}, [%4];" \
                 : "=r"(r0), "=r"(r1), "=r"(r2), "=r"(r3) : "r"(addr))
#define MMA16816(c, a, b0, b1) \
    asm volatile("mma.sync.aligned.m16n8k16.row.col.f32.bf16.bf16.f32 " \
                 "{%0,%1,%2,%3}, {%4,%5,%6,%7}, {%8,%9}, {%0,%1,%2,%3};" \
                 : "+f"((c)[0]), "+f"((c)[1]), "+f"((c)[2]), "+f"((c)[3]) \
                 : "r"((a)[0]), "r"((a)[1]), "r"((a)[2]), "r"((a)[3]), "r"(b0), "r"(b1))

// ---------------- conversion kernels ----------------
__global__ void conv_emb(const float* __restrict__ emb) {
    size_t i = (size_t)blockIdx.x * 256 + threadIdx.x;
    if (i < (size_t)Vv * Ee) {
        float x = emb[i];
        bf16 h = __float2bfloat16(x);
        g_ehi[i] = h;
        g_elo[i] = __float2bfloat16(x - __bfloat162float(h));
    }
}
__global__ void conv_w(const float* __restrict__ Wfw, const float* __restrict__ Wbw) {
    int i = blockIdx.x * 256 + threadIdx.x;
    if (i < 2 * KP * FOURH) {
        int d  = i / (KP * FOURH);
        int r  = i % (KP * FOURH);
        int kp = r / FOURH, n = r % FOURH;
        const float* W = d ? Wbw : Wfw;
        float x = W[(size_t)(kp & 255) * FOURH + n];
        bf16 hv = __float2bfloat16(x);
        g_Wt[d][kp][n] = (kp >= 256 && kp < 512)
                             ? __float2bfloat16(x - __bfloat162float(hv)) : hv;
    }
}

// ---------------- mma.sync projection GEMM (unchanged) ----------------
#define ASTR 40
#define BSTR 136

__global__ __launch_bounds__(256)
void proj_mma(const int* __restrict__ tokens) {
    __shared__ __align__(16) bf16 A_sm[128 * ASTR];
    __shared__ __align__(16) bf16 B_sm[32 * BSTR];
    __shared__ int tok[128];

    const int tid = threadIdx.x;
    const int wid = tid >> 5, lane = tid & 31;
    const int wm = wid & 3, wn = wid >> 2;
    const int n0 = blockIdx.x * 128;
    const int m0 = blockIdx.y * 128;
    const int dir = blockIdx.z;

    if (tid < 128) {
        int row = m0 + tid;
        tok[tid] = tokens[(row & 127) * Tt + (row >> 7)];
    }
    const uint32_t sbA = smem_u32(A_sm);
    const uint32_t sbB = smem_u32(B_sm);

    float c[2][8][4];
#pragma unroll
    for (int i = 0; i < 2; i++)
#pragma unroll
        for (int j = 0; j < 8; j++)
#pragma unroll
            for (int q = 0; q < 4; q++) c[i][j][q] = 0.0f;

    __syncthreads();

    for (int kt = 0; kt < 24; kt++) {
        const int kp0 = kt * 32;
        const bf16* __restrict__ Asrc = (kp0 < 512) ? g_ehi : g_elo;
        const int kb = kp0 & 255;

        uint4 av[2], bv[2];
#pragma unroll
        for (int u = 0; u < 2; u++) {
            const int q = tid + u * 256;
            const int arow = q >> 2, ac8 = q & 3;
            av[u] = *(const uint4*)(Asrc + (size_t)tok[arow] * Ee + kb + ac8 * 8);
            const int brow = q >> 4, bn8 = q & 15;
            bv[u] = *(const uint4*)(&g_Wt[dir][kp0 + brow][n0 + bn8 * 8]);
        }
        __syncthreads();
#pragma unroll
        for (int u = 0; u < 2; u++) {
            const int q = tid + u * 256;
            const int arow = q >> 2, ac8 = q & 3;
            *(uint4*)(A_sm + arow * ASTR + ac8 * 8) = av[u];
            const int brow = q >> 4, bn8 = q & 15;
            *(uint4*)(B_sm + brow * BSTR + bn8 * 8) = bv[u];
        }
        __syncthreads();

#pragma unroll
        for (int ks = 0; ks < 2; ks++) {
            uint32_t a[2][4];
#pragma unroll
            for (int i = 0; i < 2; i++) {
                const int m = wm * 32 + i * 16 + (lane & 7) + ((lane >> 3) & 1) * 8;
                const int kc = ks * 16 + (lane >> 4) * 8;
                LDSM_X4(a[i][0], a[i][1], a[i][2], a[i][3],
                        sbA + (uint32_t)(m * ASTR + kc) * 2);
            }
            uint32_t b[4][4];
#pragma unroll
            for (int j2 = 0; j2 < 4; j2++) {
                const int k = ks * 16 + (lane & 7) + ((lane >> 3) & 1) * 8;
                const int n = wn * 64 + j2 * 16 + (lane >> 4) * 8;
                LDSM_X4T(b[j2][0], b[j2][1], b[j2][2], b[j2][3],
                         sbB + (uint32_t)(k * BSTR + n) * 2);
            }
#pragma unroll
            for (int i = 0; i < 2; i++)
#pragma unroll
                for (int j = 0; j < 8; j++)
                    MMA16816(c[i][j], a[i], b[j >> 1][(j & 1) * 2], b[j >> 1][(j & 1) * 2 + 1]);
        }
    }

    const int g = lane >> 2, t2 = (lane & 3) * 2;
    float* const base = g_xw + (size_t)dir * Tt * Bb * FOURH;
#pragma unroll
    for (int i = 0; i < 2; i++) {
        const int mrow = m0 + wm * 32 + i * 16 + g;
#pragma unroll
        for (int j = 0; j < 8; j++) {
            const int col = n0 + wn * 64 + j * 8 + t2;
            float* d0 = base + (size_t)mrow * FOURH + col;
            d0[0] = c[i][j][0]; d0[1] = c[i][j][1];
            float* d1 = d0 + 8 * FOURH;
            d1[0] = c[i][j][2]; d1[1] = c[i][j][3];
        }
    }
}

// ---------------- persistent LSTM: 256 thr, k-split, mbarrier sync ----------------
#define HPAD 10
#define U2_OFF 64
#define U2_BYTES 65536
#define HBUF_OFF (U2_OFF + U2_BYTES)
#define HBUF_U64 (128 * HPAD)
#define HBUF_BYTES (2 * HBUF_U64 * 8)
#define RED_OFF (HBUF_OFF + HBUF_BYTES)
#define LSTM_SMEM (RED_OFF + 4096)

__global__ __launch_bounds__(256, 1) __cluster_dims__(4, 1, 1)
void lstm_kernel(const float* __restrict__ Ufw, const float* __restrict__ Ubw,
                 const float* __restrict__ bfw, const float* __restrict__ bbw,
                 float* __restrict__ out) {
    extern __shared__ char smem_raw[];
    ulonglong2 (*U2)[32] = (ulonglong2(*)[32])(smem_raw + U2_OFF);
    u64t* hbuf = (u64t*)(smem_raw + HBUF_OFF);
    ulonglong2* red0 = (ulonglong2*)(smem_raw + RED_OFF);
    ulonglong2* red1 = red0 + 128;
    const uint32_t sbase = smem_u32(smem_raw);
    const uint32_t hbase = sbase + HBUF_OFF;

    const int bx = blockIdx.x;
    const int dir = bx >> 6, id = bx & 63;
    const int btile = id >> 2, utile = id & 3;
    const int tid = threadIdx.x;
    const int half = tid >> 7;              // k-half
    const int ltid = tid & 127;
    const int lane = tid & 31;
    const int ul = lane >> 2, bpair = lane & 3;
    const int ju = ((ltid >> 5) << 3) + ul; // unit local 0..31
    const int j = utile * 32 + ju;
    const int bl0 = bpair * 2;
    const int b0 = btile * 8 + bl0, b1 = b0 + 1;
    const int k0 = half << 6;

    const float* __restrict__ U    = dir ? Ubw : Ufw;
    const float* __restrict__ bias = dir ? bbw : bfw;

    // U2[k][m]: gate pairs for unit (utile*32+m)
    {
        const int jg = utile * 32 + lane;
        for (int k = tid >> 5; k < 128; k += 8) {
            const float* up = U + (size_t)k * FOURH + jg;
            ulonglong2 v;
            v.x = pk2(up[0], up[128]);
            v.y = pk2(up[256], up[384]);
            U2[k][lane] = v;
        }
    }
    for (int q = tid; q < 2 * HBUF_U64; q += 256) hbuf[q] = 0ull;
    if (tid == 0) { MBAR_INIT(sbase, 4); MBAR_INIT(sbase + 8, 4); }

    const u64t bz01 = half ? 0ull : pk2(bias[j], bias[Hh + j]);
    const u64t bz23 = half ? 0ull : pk2(bias[2 * Hh + j], bias[3 * Hh + j]);

    __syncthreads();
    CLUSTER_SYNC();   // peers' mbars + zeroed buffers visible

    float c0 = 0.0f, c1 = 0.0f, hout0 = 0.0f, hout1 = 0.0f;
    const size_t xw_dir = (size_t)dir * ((size_t)Tt * Bb * FOURH);
    const uint32_t hoff0 = (uint32_t)((j * HPAD + bl0) * 8);
    const uint32_t hoff1 = hoff0 + 8u;
    const uint32_t bufB = (uint32_t)(HBUF_U64 * 8);
    uint32_t ph0 = 0, ph1 = 0;

    for (int t = 0; t < Tt; t++) {
        const int tt = dir ? (Tt - 1 - t) : t;
        const int p = t & 1;
        const u64t* __restrict__ hrd = hbuf + (size_t)p * HBUF_U64;

        // xw prefetch (half 0 only) BEFORE the sync wait — overlaps DRAM latency
        float x00, x01, x02, x03, x10, x11, x12, x13;
        if (!half) {
            const float* xwp = g_xw + xw_dir + ((size_t)tt * Bb) * FOURH;
            x00 = __ldg(xwp + (size_t)b0 * FOURH + j);
            x01 = __ldg(xwp + (size_t)b0 * FOURH + Hh + j);
            x02 = __ldg(xwp + (size_t)b0 * FOURH + 2 * Hh + j);
            x03 = __ldg(xwp + (size_t)b0 * FOURH + 3 * Hh + j);
            x10 = __ldg(xwp + (size_t)b1 * FOURH + j);
            x11 = __ldg(xwp + (size_t)b1 * FOURH + Hh + j);
            x12 = __ldg(xwp + (size_t)b1 * FOURH + 2 * Hh + j);
            x13 = __ldg(xwp + (size_t)b1 * FOURH + 3 * Hh + j);
        }

        if (t > 0) {
            if (p == 0) { mbar_wait_acq(sbase, ph0); ph0 ^= 1; }
            else        { mbar_wait_acq(sbase + 8, ph1); ph1 ^= 1; }
        }

        u64t acc01_0 = bz01, acc23_0 = bz23;
        u64t acc01_1 = bz01, acc23_1 = bz23;
#pragma unroll 16
        for (int kk = 0; kk < 64; kk++) {
            const int k = k0 + kk;
            const ulonglong2 u = U2[k][ju];
            const ulonglong2 hh = *(const ulonglong2*)(hrd + k * HPAD + bl0);
            FFMA2(acc01_0, hh.x, u.x);
            FFMA2(acc23_0, hh.x, u.y);
            FFMA2(acc01_1, hh.y, u.x);
            FFMA2(acc23_1, hh.y, u.y);
        }

        if (half) {
            red0[ltid] = make_ulonglong2(acc01_0, acc23_0);
            red1[ltid] = make_ulonglong2(acc01_1, acc23_1);
        }
        __syncthreads();

        if (!half) {
            const ulonglong2 r0 = red0[ltid];
            const ulonglong2 r1 = red1[ltid];
            ADDF2(acc01_0, r0.x); ADDF2(acc23_0, r0.y);
            ADDF2(acc01_1, r1.x); ADDF2(acc23_1, r1.y);

            float a00, a01, a02, a03, a10, a11, a12, a13;
            upk2(acc01_0, a00, a01); upk2(acc23_0, a02, a03);
            upk2(acc01_1, a10, a11); upk2(acc23_1, a12, a13);
            a00 += x00; a01 += x01; a02 += x02; a03 += x03;
            a10 += x10; a11 += x11; a12 += x12; a13 += x13;
            {
                const float ig = sigmoid_f(a00), fg = sigmoid_f(a01);
                const float gg = tanh_f(a02), og = sigmoid_f(a03);
                c0 = fg * c0 + ig * gg;
                hout0 = og * tanh_f(c0);
            }
            {
                const float ig = sigmoid_f(a10), fg = sigmoid_f(a11);
                const float gg = tanh_f(a12), og = sigmoid_f(a13);
                c1 = fg * c1 + ig * gg;
                hout1 = og * tanh_f(c1);
            }
            // publish h into buffer p^1 of all 4 cluster CTAs
            const uint32_t wb = hbase + (p ? 0u : bufB);
            const u64t v0 = pk2(hout0, hout0);
            const u64t v1 = pk2(hout1, hout1);
#pragma unroll
            for (int r = 0; r < 4; r++) {
                st_cluster_u64(wb + hoff0, r, v0);
                st_cluster_u64(wb + hoff1, r, v1);
            }
        }
        __syncthreads();           // all half-0 stores issued & ordered
        if (tid < 4) {
            const uint32_t mb = sbase + (uint32_t)((p ^ 1) * 8);
            mbar_arrive_rel(mb, tid);
        }
        if (!half) {
            out[((size_t)b0 * Tt + tt) * 256 + dir * Hh + j] = hout0;
            out[((size_t)b1 * Tt + tt) * 256 + dir * Hh + j] = hout1;
        }
    }

    if (!half) {
        const size_t fin = (size_t)Bb * Tt * 256 + (size_t)dir * 2 * Bb * Hh;
        out[fin + (size_t)b0 * Hh + j] = hout0;
        out[fin + (size_t)b1 * Hh + j] = hout1;
        out[fin + Bb * Hh + (size_t)b0 * Hh + j] = c0;
        out[fin + Bb * Hh + (size_t)b1 * Hh + j] = c1;
    }
    CLUSTER_SYNC();   // no CTA exits while peers may still DSMEM-write here
}

// ---------------- launch ----------------
extern "C" void kernel_launch(void* const* d_in, const int* in_sizes, int n_in,
                              void* d_out, int out_size) {
    const int*   tokens = (const int*)d_in[0];
    const float* emb    = (const float*)d_in[1];
    const float* Wfw    = (const float*)d_in[2];
    const float* Ufw    = (const float*)d_in[3];
    const float* bfw    = (const float*)d_in[4];
    const float* Wbw    = (const float*)d_in[5];
    const float* Ubw    = (const float*)d_in[6];
    const float* bbw    = (const float*)d_in[7];
    float* out = (float*)d_out;

    static bool attr_set = false;
    if (!attr_set) {
        cudaFuncSetAttribute(lstm_kernel, cudaFuncAttributeMaxDynamicSharedMemorySize, (int)LSTM_SMEM);
        attr_set = true;
    }

    conv_emb<<<(Vv * Ee + 255) / 256, 256>>>(emb);
    conv_w<<<(2 * KP * FOURH + 255) / 256, 256>>>(Wfw, Wbw);
    proj_mma<<<dim3(4, 512, 2), 256>>>(tokens);
    lstm_kernel<<<128, 256, LSTM_SMEM>>>(Ufw, Ubw, bfw, bbw, out);
}